// round 11
// baseline (speedup 1.0000x reference)
#include <cuda_runtime.h>
#include <cstdint>
#include <cstddef>

// Problem constants
#define B_  256
#define T_  1024
#define I_  8
#define H_  256
#define L_  32          // steps per chunk
#define C_  32          // number of chunks (C_*L_ == T_)
#define BH  (B_*H_)
#define R_  64          // batch rows per scan CTA
#define NRG (B_/R_)     // 4 row groups -> 128 scan CTAs

// ---------------- device scratch (no allocations allowed) ----------------
__device__ float g_At[H_ * H_];              // A = Wh^T  (h_new = h @ A)
__device__ float g_T1[H_ * H_];
__device__ float g_T2[H_ * H_];
__device__ float g_P32[H_ * H_];             // A^32
__device__ float g_Zend[(size_t)C_ * BH];    // chunk-final partials (zero-init scans)
__device__ float g_Hstart[(size_t)C_ * BH];  // true chunk start states

// ---------------- packed f32x2 helpers ----------------
__device__ __forceinline__ unsigned long long pack2(float v) {
    unsigned long long r;
    asm("mov.b64 %0, {%1, %1};" : "=l"(r) : "f"(v));
    return r;
}
__device__ __forceinline__ void fma2(unsigned long long& d,
                                     unsigned long long a,
                                     unsigned long long b) {
    asm("fma.rn.f32x2 %0, %1, %2, %0;" : "+l"(d) : "l"(a), "l"(b));
}
__device__ __forceinline__ float lof(unsigned long long v) {
    return __uint_as_float((unsigned)v);
}
__device__ __forceinline__ float hif(unsigned long long v) {
    return __uint_as_float((unsigned)(v >> 32));
}

// ---------------- out[0] = broadcast h0 ----------------
__global__ void k_out0(float* __restrict__ out, const float* __restrict__ h0) {
    int idx = blockIdx.x * 256 + threadIdx.x;           // 65536 total
    out[idx] = h0[idx & (H_ - 1)];
}

// ---------------- g_At = Wh^T ----------------
__global__ void k_transpose(const float* __restrict__ Wh) {
    int idx = blockIdx.x * 256 + threadIdx.x;   // 65536
    int h  = idx >> 8;
    int h2 = idx & 255;
    g_At[idx] = Wh[h2 * H_ + h];                // A[h][h'] = Wh[h'][h]
}

// ---------------- squaring chain for A^32 ----------------
__global__ void k_square(int step) {
    const float* src;
    float* dst;
    switch (step) {
        case 0: src = g_At; dst = g_T1;  break;   // A^2
        case 1: src = g_T1; dst = g_T2;  break;   // A^4
        case 2: src = g_T2; dst = g_T1;  break;   // A^8
        case 3: src = g_T1; dst = g_T2;  break;   // A^16
        default:src = g_T2; dst = g_P32; break;   // A^32
    }
    __shared__ float as[32][33], bs[32][33];
    const int tx = threadIdx.x & 31;
    const int ty = threadIdx.x >> 5;            // 0..7
    const int row0 = blockIdx.y * 32, col0 = blockIdx.x * 32;
    float acc[4] = {0.f, 0.f, 0.f, 0.f};
    for (int k0 = 0; k0 < H_; k0 += 32) {
#pragma unroll
        for (int e = 0; e < 4; e++) {
            int r = ty + e * 8;
            as[r][tx] = src[(size_t)(row0 + r) * H_ + k0 + tx];
            bs[r][tx] = src[(size_t)(k0 + r) * H_ + col0 + tx];
        }
        __syncthreads();
#pragma unroll
        for (int kk = 0; kk < 32; kk++) {
            float bv = bs[kk][tx];
#pragma unroll
            for (int e = 0; e < 4; e++) acc[e] += as[ty + e * 8][kk] * bv;
        }
        __syncthreads();
    }
#pragma unroll
    for (int e = 0; e < 4; e++)
        dst[(size_t)(row0 + ty + e * 8) * H_ + col0 + tx] = acc[e];
}

// ---------------- chunked scan, fused input projection, barrier-free steps ----
// R_=64 rows/CTA, 128 CTAs, 1 CTA/SM, 8 warps. Warp tile: 8 rows x 256 cols
// (lane cols {4l..4l+3, 128+4l..128+4l+3}) -> each warp reads/writes ONLY its
// own 8 z-rows: warps are independent, steps need __syncwarp() only.
// xw is computed on the fly: Wx staged in smem once; x slice (8 rows x 8) staged
// warp-privately per step (double-buffered). No g_xw array at all.
// PASS 0: zero-init scan, stores only Zend. PASS 1: from Hstart, writes out.
template <int PASS>
__global__ void __launch_bounds__(256, 1) k_scan(const float* __restrict__ x,
                                                 const float* __restrict__ Wxg,
                                                 float* __restrict__ out) {
    extern __shared__ float sm[];
    float* zb[2] = { sm, sm + R_ * H_ };          // 2 x 64KB
    float* Wxs   = sm + 2 * R_ * H_;              // [I_][H_] 8KB
    float* xsb   = Wxs + I_ * H_;                 // [2][R_][I_] 2x2KB

    const int c    = blockIdx.x & (C_ - 1);   // chunk
    const int rg   = blockIdx.x >> 5;         // row group 0..3
    const int r0   = rg * R_;
    const int tau  = threadIdx.x;
    const int w    = tau >> 5;                // warp id 0..7 -> 8 rows each
    const int l    = tau & 31;
    const int cA   = l * 4;                   // low 4 columns
    const int cB   = 128 + l * 4;             // high 4 columns
    const int srow = w * 8 + (l >> 2);        // staging row for this lane
    const int sii  = (l & 3) * 2;             // staging float2 offset

    // ---- prologue (block-cooperative parts) ----
    // Wxs[i][h] = Wx[h][i]
#pragma unroll
    for (int k = tau; k < I_ * H_; k += 256) {
        int i = k >> 8, h = k & 255;
        Wxs[k] = Wxg[h * I_ + i];
    }
    if (PASS == 1) {
        const unsigned long long* s = (const unsigned long long*)
            (g_Hstart + (size_t)c * BH + (size_t)r0 * H_);
        unsigned long long* d = (unsigned long long*)zb[0];
#pragma unroll
        for (int k = 0; k < 32; k++) d[tau + k * 256] = s[tau + k * 256];
    }
    __syncthreads();

    // warp-private x staging: xs[buf][srow][8] for time step t (x index t-1)
    auto stage = [&](int buf, int t) {
        const float2 v = *(const float2*)
            (x + ((size_t)(r0 + srow) * T_ + (t - 1)) * I_ + sii);
        *(float2*)&xsb[buf * (R_ * I_) + srow * I_ + sii] = v;
        __syncwarp();
    };

    // compute xw contribution for this thread's 8 rows x 8 cols into acc
    auto fuse_xw = [&](int buf, unsigned long long (&acc)[8][4]) {
        ulonglong2 wxa[I_], wxb[I_];
#pragma unroll
        for (int i = 0; i < I_; i++) {
            wxa[i] = *(const ulonglong2*)&Wxs[i * H_ + cA];
            wxb[i] = *(const ulonglong2*)&Wxs[i * H_ + cB];
        }
#pragma unroll
        for (int r = 0; r < 8; r++) {
            const float* xr = &xsb[buf * (R_ * I_) + (w * 8 + r) * I_];
            float4 xa = *(const float4*)xr;
            float4 xbv = *(const float4*)(xr + 4);
            acc[r][0] = acc[r][1] = acc[r][2] = acc[r][3] = 0ull;
            float xv[8] = { xa.x, xa.y, xa.z, xa.w, xbv.x, xbv.y, xbv.z, xbv.w };
#pragma unroll
            for (int i = 0; i < I_; i++) {
                unsigned long long zz = pack2(xv[i]);
                fma2(acc[r][0], zz, wxa[i].x);
                fma2(acc[r][1], zz, wxa[i].y);
                fma2(acc[r][2], zz, wxb[i].x);
                fma2(acc[r][3], zz, wxb[i].y);
            }
        }
    };

    int p = 0;
    const int jstart = (PASS == 0) ? 2 : 1;

    if (PASS == 0) {
        // zb[0] = xw(t = c*L+1)  (state after step 1 from zero init)
        stage(1, c * L_ + 1);
        unsigned long long acc0[8][4];
        fuse_xw(1, acc0);
#pragma unroll
        for (int i = 0; i < 8; i++) {
            float* zw = zb[0] + (w * 8 + i) * H_;
            *(ulonglong2*)(zw + cA) = make_ulonglong2(acc0[i][0], acc0[i][1]);
            *(ulonglong2*)(zw + cB) = make_ulonglong2(acc0[i][2], acc0[i][3]);
        }
        __syncwarp();
    }
    stage(jstart & 1, c * L_ + jstart);

    for (int j = jstart; j <= L_; ++j) {
        const int t = c * L_ + j;             // global time step (1..T)
        unsigned long long acc[8][4];
        fuse_xw(j & 1, acc);                  // acc = xw_t (i-order 0..7)
        if (j < L_) stage((j + 1) & 1, t + 1);

        const float* zrow = zb[p] + w * 8 * H_;
#pragma unroll 2
        for (int hg = 0; hg < H_ / 4; ++hg) {
            float4 z4[8];
#pragma unroll
            for (int i = 0; i < 8; i++)
                z4[i] = *(const float4*)(zrow + i * H_ + hg * 4);
#pragma unroll
            for (int hh = 0; hh < 4; hh++) {
                const float* arow = g_At + (hg * 4 + hh) * H_;
                ulonglong2 a_lo = *(const ulonglong2*)(arow + cA);
                ulonglong2 a_hi = *(const ulonglong2*)(arow + cB);
#pragma unroll
                for (int i = 0; i < 8; i++) {
                    float zv = (hh == 0) ? z4[i].x
                             : (hh == 1) ? z4[i].y
                             : (hh == 2) ? z4[i].z : z4[i].w;
                    unsigned long long zz = pack2(zv);
                    fma2(acc[i][0], zz, a_lo.x);
                    fma2(acc[i][1], zz, a_lo.y);
                    fma2(acc[i][2], zz, a_hi.x);
                    fma2(acc[i][3], zz, a_hi.y);
                }
            }
        }
#pragma unroll
        for (int i = 0; i < 8; i++) {
            float* zw = zb[p ^ 1] + (w * 8 + i) * H_;
            *(ulonglong2*)(zw + cA) = make_ulonglong2(acc[i][0], acc[i][1]);
            *(ulonglong2*)(zw + cB) = make_ulonglong2(acc[i][2], acc[i][3]);
            if (PASS == 1) {
                float* o = out + (size_t)t * BH + (size_t)(r0 + w * 8 + i) * H_;
                __stcs((float4*)(o + cA),
                       make_float4(lof(acc[i][0]), hif(acc[i][0]),
                                   lof(acc[i][1]), hif(acc[i][1])));
                __stcs((float4*)(o + cB),
                       make_float4(lof(acc[i][2]), hif(acc[i][2]),
                                   lof(acc[i][3]), hif(acc[i][3])));
            }
        }
        __syncwarp();                         // own-rows only: warp-local hazard
        p ^= 1;
    }

    if (PASS == 0) {
        __syncthreads();                      // all warps' final z in place
        const unsigned long long* s = (const unsigned long long*)zb[p];
        unsigned long long* d = (unsigned long long*)
            (g_Zend + (size_t)c * BH + (size_t)r0 * H_);
#pragma unroll
        for (int k = 0; k < 32; k++) d[tau + k * 256] = s[tau + k * 256];
    }
}

// ---------------- carry: Hstart[c+1] = Hstart[c] @ A^32 + Zend[c] ----------------
__global__ void __launch_bounds__(256, 1) k_carry(const float* __restrict__ h0) {
    __shared__ float hb[2][4 * H_];
    const int r0   = blockIdx.x * 4;          // 64 blocks x 4 rows
    const int tau  = threadIdx.x;
    const int rowg = tau >> 6;                // 0..3
    const int lg   = tau & 63;
    const int c0   = lg * 4;                  // 4 output cols per thread (coalesced)

    // Hstart[0] = broadcast h0
#pragma unroll
    for (int e = 0; e < 4; e++) {
        float v = h0[tau];
        hb[0][e * H_ + tau] = v;
        g_Hstart[(size_t)(r0 + e) * H_ + tau] = v;
    }
    __syncthreads();

    int p = 0;
    for (int c = 0; c < C_ - 1; c++) {
        unsigned long long acc[2];
        const unsigned long long* zs = (const unsigned long long*)
            (g_Zend + (size_t)c * BH + (size_t)(r0 + rowg) * H_ + c0);
        acc[0] = zs[0]; acc[1] = zs[1];
        const float* zr = hb[p] + rowg * H_;
#pragma unroll 4
        for (int h = 0; h < H_; h++) {
            ulonglong2 aa = *(const ulonglong2*)(g_P32 + h * H_ + c0);
            unsigned long long zz = pack2(zr[h]);
            fma2(acc[0], zz, aa.x);
            fma2(acc[1], zz, aa.y);
        }
        unsigned long long* w = (unsigned long long*)(hb[p ^ 1] + rowg * H_ + c0);
        w[0] = acc[0]; w[1] = acc[1];
        unsigned long long* g = (unsigned long long*)
            (g_Hstart + (size_t)(c + 1) * BH + (size_t)(r0 + rowg) * H_ + c0);
        g[0] = acc[0]; g[1] = acc[1];
        __syncthreads();
        p ^= 1;
    }
}

// ---------------- launch ----------------
extern "C" void kernel_launch(void* const* d_in, const int* in_sizes, int n_in,
                              void* d_out, int out_size) {
    (void)in_sizes; (void)n_in; (void)out_size;
    const float* x  = (const float*)d_in[0];
    const float* Wh = (const float*)d_in[1];
    const float* Wx = (const float*)d_in[2];
    const float* h0 = (const float*)d_in[3];
    float* out = (float*)d_out;

    const int smem = (2 * R_ * H_ + I_ * H_ + 2 * R_ * I_) * (int)sizeof(float);
    cudaFuncSetAttribute(k_scan<0>, cudaFuncAttributeMaxDynamicSharedMemorySize, smem);
    cudaFuncSetAttribute(k_scan<1>, cudaFuncAttributeMaxDynamicSharedMemorySize, smem);

    // ncu captures MY 0-based launch index 3 -> keep k_scan<0> there.
    k_transpose<<<256, 256>>>(Wh);                     // 0
    k_out0<<<256, 256>>>(out, h0);                     // 1
    dim3 g8(8, 8);
    k_square<<<g8, 256>>>(0);                          // 2  A^2
    k_scan<0><<<C_ * NRG, 256, smem>>>(x, Wx, out);    // 3  partials -> Zend (PROFILED)
    k_square<<<g8, 256>>>(1);                          // 4  A^4
    k_square<<<g8, 256>>>(2);                          // 5  A^8
    k_square<<<g8, 256>>>(3);                          // 6  A^16
    k_square<<<g8, 256>>>(4);                          // 7  A^32
    k_carry<<<B_ / 4, 256>>>(h0);                      // 8  chunk start states
    k_scan<1><<<C_ * NRG, 256, smem>>>(x, Wx, out);    // 9  final scan -> out
}

// round 12
// speedup vs baseline: 1.5489x; 1.5489x over previous
#include <cuda_runtime.h>
#include <cstdint>
#include <cstddef>

// Problem constants
#define B_  256
#define T_  1024
#define I_  8
#define H_  256
#define L_  32          // steps per chunk
#define C_  32          // number of chunks (C_*L_ == T_)
#define BH  (B_*H_)
#define R_  64          // batch rows per scan CTA
#define NRG (B_/R_)     // 4 row groups -> 128 scan CTAs

// ---------------- device scratch (no allocations allowed) ----------------
__device__ float g_xw[(size_t)T_ * BH];      // input projections xw[t][b][h]
__device__ float g_At[H_ * H_];              // A = Wh^T  (h_new = h @ A)
__device__ float g_T1[H_ * H_];
__device__ float g_T2[H_ * H_];
__device__ float g_P32[H_ * H_];             // A^32
__device__ float g_Zend[(size_t)C_ * BH];    // chunk-final partials (zero-init scans)
__device__ float g_Hstart[(size_t)C_ * BH];  // true chunk start states

// ---------------- packed f32x2 helpers ----------------
__device__ __forceinline__ unsigned long long pack2(float v) {
    unsigned long long r;
    asm("mov.b64 %0, {%1, %1};" : "=l"(r) : "f"(v));
    return r;
}
__device__ __forceinline__ void fma2(unsigned long long& d,
                                     unsigned long long a,
                                     unsigned long long b) {
    asm("fma.rn.f32x2 %0, %1, %2, %0;" : "+l"(d) : "l"(a), "l"(b));
}
__device__ __forceinline__ float lof(unsigned long long v) {
    return __uint_as_float((unsigned)v);
}
__device__ __forceinline__ float hif(unsigned long long v) {
    return __uint_as_float((unsigned)(v >> 32));
}

// ---------------- out[0] = broadcast h0 ----------------
__global__ void k_out0(float* __restrict__ out, const float* __restrict__ h0) {
    int idx = blockIdx.x * 256 + threadIdx.x;           // 65536 total
    out[idx] = h0[idx & (H_ - 1)];
}

// ---------------- xw[t] = x[:,t,:] @ Wx^T ----------------
__global__ void k_xw(const float* __restrict__ x, const float* __restrict__ Wx) {
    const int t   = blockIdx.x;       // 0..T-1
    const int tau = threadIdx.x;      // = output h index
    float wx[I_];
#pragma unroll
    for (int i = 0; i < I_; i++) wx[i] = Wx[tau * I_ + i];

    __shared__ float xs[32][I_];
    const int br = tau >> 3;          // 0..31
    const int ii = tau & 7;

    for (int b0 = 0; b0 < B_; b0 += 32) {
        xs[br][ii] = x[((size_t)(b0 + br) * T_ + t) * I_ + ii];
        __syncthreads();
#pragma unroll 4
        for (int bb = 0; bb < 32; bb++) {
            float s = 0.f;
#pragma unroll
            for (int i = 0; i < I_; i++) s += xs[bb][i] * wx[i];
            __stcs(&g_xw[((size_t)t * B_ + (b0 + bb)) * H_ + tau], s);
        }
        __syncthreads();
    }
}

// ---------------- g_At = Wh^T ----------------
__global__ void k_transpose(const float* __restrict__ Wh) {
    int idx = blockIdx.x * 256 + threadIdx.x;   // 65536
    int h  = idx >> 8;
    int h2 = idx & 255;
    g_At[idx] = Wh[h2 * H_ + h];                // A[h][h'] = Wh[h'][h]
}

// ---------------- squaring chain for A^32 ----------------
__global__ void k_square(int step) {
    const float* src;
    float* dst;
    switch (step) {
        case 0: src = g_At; dst = g_T1;  break;   // A^2
        case 1: src = g_T1; dst = g_T2;  break;   // A^4
        case 2: src = g_T2; dst = g_T1;  break;   // A^8
        case 3: src = g_T1; dst = g_T2;  break;   // A^16
        default:src = g_T2; dst = g_P32; break;   // A^32
    }
    __shared__ float as[32][33], bs[32][33];
    const int tx = threadIdx.x & 31;
    const int ty = threadIdx.x >> 5;            // 0..7
    const int row0 = blockIdx.y * 32, col0 = blockIdx.x * 32;
    float acc[4] = {0.f, 0.f, 0.f, 0.f};
    for (int k0 = 0; k0 < H_; k0 += 32) {
#pragma unroll
        for (int e = 0; e < 4; e++) {
            int r = ty + e * 8;
            as[r][tx] = src[(size_t)(row0 + r) * H_ + k0 + tx];
            bs[r][tx] = src[(size_t)(k0 + r) * H_ + col0 + tx];
        }
        __syncthreads();
#pragma unroll
        for (int kk = 0; kk < 32; kk++) {
            float bv = bs[kk][tx];
#pragma unroll
            for (int e = 0; e < 4; e++) acc[e] += as[ty + e * 8][kk] * bv;
        }
        __syncthreads();
    }
#pragma unroll
    for (int e = 0; e < 4; e++)
        dst[(size_t)(row0 + ty + e * 8) * H_ + col0 + tx] = acc[e];
}

// ---------------- chunked scan (barrier-free steps, single z buffer) -------
// R_=64 rows/CTA, 128 CTAs, 1 CTA/SM, 8 warps. Warp tile: 8 rows x 256 cols
// (lane cols {4l..4l+3, 128+4l..128+4l+3}) -> each warp reads/writes ONLY its
// own 8 z-rows: warps are fully independent; steps use __syncwarp() only.
// Single z buffer (64 KB smem): within a warp all step-j z reads precede the
// step-j z writes in the one instruction stream, so no double buffer needed.
// Bigger L1 carveout (~164 KB) keeps most of A (256 KB) resident.
// PASS 0: zero-init scan, stores only Zend. PASS 1: from Hstart, writes out.
template <int PASS>
__global__ void __launch_bounds__(256, 1) k_scan(float* __restrict__ out) {
    extern __shared__ float zb[];             // [R_][H_] 64 KB

    const int c    = blockIdx.x & (C_ - 1);   // chunk
    const int rg   = blockIdx.x >> 5;         // row group 0..3
    const int r0   = rg * R_;
    const int tau  = threadIdx.x;
    const int w    = tau >> 5;                // warp id 0..7 -> 8 rows each
    const int l    = tau & 31;
    const int cA   = l * 4;                   // low 4 columns
    const int cB   = 128 + l * 4;             // high 4 columns

    // init z buffer: PASS0 -> xw of first step; PASS1 -> Hstart (coalesced copy)
    {
        const float* src = (PASS == 0)
            ? (g_xw + (size_t)(c * L_) * BH + (size_t)r0 * H_)
            : (g_Hstart + (size_t)c * BH + (size_t)r0 * H_);
        const unsigned long long* s = (const unsigned long long*)src;
        unsigned long long* d = (unsigned long long*)zb;
#pragma unroll
        for (int k = 0; k < 32; k++) d[tau + k * 256] = s[tau + k * 256];
    }
    __syncthreads();

    const int jstart = (PASS == 0) ? 2 : 1;

    for (int j = jstart; j <= L_; ++j) {
        const int t = c * L_ + j;             // global time step (1..T)
        unsigned long long acc[8][4];         // 8 rows x 4 col-u64
#pragma unroll
        for (int i = 0; i < 8; i++) {
            const float* xr = g_xw + (size_t)(t - 1) * BH
                                   + (size_t)(r0 + w * 8 + i) * H_;
            float4 xlo = __ldcs((const float4*)(xr + cA));
            float4 xhi = __ldcs((const float4*)(xr + cB));
            acc[i][0] = ((unsigned long long)__float_as_uint(xlo.y) << 32) | __float_as_uint(xlo.x);
            acc[i][1] = ((unsigned long long)__float_as_uint(xlo.w) << 32) | __float_as_uint(xlo.z);
            acc[i][2] = ((unsigned long long)__float_as_uint(xhi.y) << 32) | __float_as_uint(xhi.x);
            acc[i][3] = ((unsigned long long)__float_as_uint(xhi.w) << 32) | __float_as_uint(xhi.z);
        }
        const float* zrow = zb + w * 8 * H_;

#pragma unroll 2
        for (int hg = 0; hg < H_ / 4; ++hg) {      // groups of 4 h
            float4 z4[8];
#pragma unroll
            for (int i = 0; i < 8; i++)
                z4[i] = *(const float4*)(zrow + i * H_ + hg * 4);
#pragma unroll
            for (int hh = 0; hh < 4; hh++) {
                const float* arow = g_At + (hg * 4 + hh) * H_;
                ulonglong2 a_lo = *(const ulonglong2*)(arow + cA);
                ulonglong2 a_hi = *(const ulonglong2*)(arow + cB);
#pragma unroll
                for (int i = 0; i < 8; i++) {
                    float zv = (hh == 0) ? z4[i].x
                             : (hh == 1) ? z4[i].y
                             : (hh == 2) ? z4[i].z : z4[i].w;
                    unsigned long long zz = pack2(zv);
                    fma2(acc[i][0], zz, a_lo.x);
                    fma2(acc[i][1], zz, a_lo.y);
                    fma2(acc[i][2], zz, a_hi.x);
                    fma2(acc[i][3], zz, a_hi.y);
                }
            }
        }
#pragma unroll
        for (int i = 0; i < 8; i++) {
            float* zw = zb + (w * 8 + i) * H_;
            *(ulonglong2*)(zw + cA) = make_ulonglong2(acc[i][0], acc[i][1]);
            *(ulonglong2*)(zw + cB) = make_ulonglong2(acc[i][2], acc[i][3]);
            if (PASS == 1) {
                float* o = out + (size_t)t * BH + (size_t)(r0 + w * 8 + i) * H_;
                __stcs((float4*)(o + cA),
                       make_float4(lof(acc[i][0]), hif(acc[i][0]),
                                   lof(acc[i][1]), hif(acc[i][1])));
                __stcs((float4*)(o + cB),
                       make_float4(lof(acc[i][2]), hif(acc[i][2]),
                                   lof(acc[i][3]), hif(acc[i][3])));
            }
        }
        __syncwarp();                          // warp-local ordering only
    }

    if (PASS == 0) {
        __syncthreads();                       // all warps' final z in place
        const unsigned long long* s = (const unsigned long long*)zb;
        unsigned long long* d = (unsigned long long*)
            (g_Zend + (size_t)c * BH + (size_t)r0 * H_);
#pragma unroll
        for (int k = 0; k < 32; k++) d[tau + k * 256] = s[tau + k * 256];
    }
}

// ---------------- carry: Hstart[c+1] = Hstart[c] @ A^32 + Zend[c] ----------------
__global__ void __launch_bounds__(256, 1) k_carry(const float* __restrict__ h0) {
    __shared__ float hb[2][4 * H_];
    const int r0   = blockIdx.x * 4;          // 64 blocks x 4 rows
    const int tau  = threadIdx.x;
    const int rowg = tau >> 6;                // 0..3
    const int lg   = tau & 63;
    const int c0   = lg * 4;                  // 4 output cols per thread (coalesced)

    // Hstart[0] = broadcast h0
#pragma unroll
    for (int e = 0; e < 4; e++) {
        float v = h0[tau];
        hb[0][e * H_ + tau] = v;
        g_Hstart[(size_t)(r0 + e) * H_ + tau] = v;
    }
    __syncthreads();

    int p = 0;
    for (int c = 0; c < C_ - 1; c++) {
        unsigned long long acc[2];
        const unsigned long long* zs = (const unsigned long long*)
            (g_Zend + (size_t)c * BH + (size_t)(r0 + rowg) * H_ + c0);
        acc[0] = zs[0]; acc[1] = zs[1];
        const float* zr = hb[p] + rowg * H_;
#pragma unroll 4
        for (int h = 0; h < H_; h++) {
            ulonglong2 aa = *(const ulonglong2*)(g_P32 + h * H_ + c0);
            unsigned long long zz = pack2(zr[h]);
            fma2(acc[0], zz, aa.x);
            fma2(acc[1], zz, aa.y);
        }
        unsigned long long* w = (unsigned long long*)(hb[p ^ 1] + rowg * H_ + c0);
        w[0] = acc[0]; w[1] = acc[1];
        unsigned long long* g = (unsigned long long*)
            (g_Hstart + (size_t)(c + 1) * BH + (size_t)(r0 + rowg) * H_ + c0);
        g[0] = acc[0]; g[1] = acc[1];
        __syncthreads();
        p ^= 1;
    }
}

// ---------------- launch ----------------
extern "C" void kernel_launch(void* const* d_in, const int* in_sizes, int n_in,
                              void* d_out, int out_size) {
    (void)in_sizes; (void)n_in; (void)out_size;
    const float* x  = (const float*)d_in[0];
    const float* Wh = (const float*)d_in[1];
    const float* Wx = (const float*)d_in[2];
    const float* h0 = (const float*)d_in[3];
    float* out = (float*)d_out;

    const int smem = R_ * H_ * (int)sizeof(float);   // 65536 bytes
    cudaFuncSetAttribute(k_scan<0>, cudaFuncAttributeMaxDynamicSharedMemorySize, smem);
    cudaFuncSetAttribute(k_scan<1>, cudaFuncAttributeMaxDynamicSharedMemorySize, smem);

    // ncu captures MY 0-based launch index 3 -> keep k_scan<0> there.
    k_xw<<<T_, 256>>>(x, Wx);                          // 0
    k_transpose<<<256, 256>>>(Wh);                     // 1
    k_out0<<<256, 256>>>(out, h0);                     // 2
    k_scan<0><<<C_ * NRG, 256, smem>>>(out);           // 3  partials -> Zend (PROFILED)
    dim3 g8(8, 8);
    k_square<<<g8, 256>>>(0);                          // 4  A^2
    k_square<<<g8, 256>>>(1);                          // 5  A^4
    k_square<<<g8, 256>>>(2);                          // 6  A^8
    k_square<<<g8, 256>>>(3);                          // 7  A^16
    k_square<<<g8, 256>>>(4);                          // 8  A^32
    k_carry<<<B_ / 4, 256>>>(h0);                      // 9  chunk start states
    k_scan<1><<<C_ * NRG, 256, smem>>>(out);           // 10 final scan -> out
}

// round 13
// speedup vs baseline: 1.5534x; 1.0029x over previous
#include <cuda_runtime.h>
#include <cstdint>
#include <cstddef>

// Problem constants
#define B_  256
#define T_  1024
#define I_  8
#define H_  256
#define HA  (H_ + I_)   // augmented state width: [h | x] = 264
#define L_  32          // steps per chunk
#define C_  32          // number of chunks (C_*L_ == T_)
#define BH  (B_*H_)
#define R_  64          // batch rows per scan CTA
#define NRG (B_/R_)     // 4 row groups -> 128 scan CTAs

// ---------------- device scratch (no allocations allowed) ----------------
__device__ float g_Aaug[HA * H_];            // rows 0..255: Wh^T ; rows 256..263: Wx^T
__device__ float g_xt[(size_t)T_ * B_ * I_]; // x transposed to (T,B,I), 8 MB
__device__ float g_T1[H_ * H_];
__device__ float g_T2[H_ * H_];
__device__ float g_P32[H_ * H_];             // (Wh^T)^32
__device__ float g_Zend[(size_t)C_ * BH];    // chunk-final partials (zero-init scans)
__device__ float g_Hstart[(size_t)C_ * BH];  // true chunk start states

// ---------------- packed f32x2 helpers ----------------
__device__ __forceinline__ unsigned long long pack2(float v) {
    unsigned long long r;
    asm("mov.b64 %0, {%1, %1};" : "=l"(r) : "f"(v));
    return r;
}
__device__ __forceinline__ void fma2(unsigned long long& d,
                                     unsigned long long a,
                                     unsigned long long b) {
    asm("fma.rn.f32x2 %0, %1, %2, %0;" : "+l"(d) : "l"(a), "l"(b));
}
__device__ __forceinline__ float lof(unsigned long long v) {
    return __uint_as_float((unsigned)v);
}
__device__ __forceinline__ float hif(unsigned long long v) {
    return __uint_as_float((unsigned)(v >> 32));
}

// ---------------- out[0] = broadcast h0 ----------------
__global__ void k_out0(float* __restrict__ out, const float* __restrict__ h0) {
    int idx = blockIdx.x * 256 + threadIdx.x;           // 65536 total
    out[idx] = h0[idx & (H_ - 1)];
}

// ---------------- xt[t][b][i] = x[b][t][i]  (write-coalesced) ----------------
__global__ void k_xt(const float* __restrict__ x) {
    int idx = blockIdx.x * 256 + threadIdx.x;           // 2M elements
    int i = idx & (I_ - 1);
    int b = (idx >> 3) & (B_ - 1);
    int t = idx >> 11;
    g_xt[idx] = x[((size_t)b * T_ + t) * I_ + i];
}

// ---------------- build A_aug: rows 0..255 = Wh^T, rows 256..263 = Wx^T ------
__global__ void k_prep(const float* __restrict__ Wh, const float* __restrict__ Wx) {
    int idx = blockIdx.x * 256 + threadIdx.x;           // HA*H_ = 67584
    if (idx < H_ * H_) {
        int h  = idx >> 8;
        int c  = idx & 255;
        g_Aaug[idx] = Wh[c * H_ + h];                   // (Wh^T)[h][c]
    } else if (idx < HA * H_) {
        int r  = idx >> 8;                              // 256..263
        int c  = idx & 255;
        g_Aaug[idx] = Wx[c * I_ + (r - H_)];            // (Wx^T)[i][c]
    }
}

// ---------------- squaring chain for (Wh^T)^32 ----------------
__global__ void k_square(int step) {
    const float* src;
    float* dst;
    switch (step) {
        case 0: src = g_Aaug; dst = g_T1;  break;  // A^2 (first 256 rows of Aaug = Wh^T)
        case 1: src = g_T1;   dst = g_T2;  break;  // A^4
        case 2: src = g_T2;   dst = g_T1;  break;  // A^8
        case 3: src = g_T1;   dst = g_T2;  break;  // A^16
        default:src = g_T2;   dst = g_P32; break;  // A^32
    }
    __shared__ float as[32][33], bs[32][33];
    const int tx = threadIdx.x & 31;
    const int ty = threadIdx.x >> 5;            // 0..7
    const int row0 = blockIdx.y * 32, col0 = blockIdx.x * 32;
    float acc[4] = {0.f, 0.f, 0.f, 0.f};
    for (int k0 = 0; k0 < H_; k0 += 32) {
#pragma unroll
        for (int e = 0; e < 4; e++) {
            int r = ty + e * 8;
            as[r][tx] = src[(size_t)(row0 + r) * H_ + k0 + tx];
            bs[r][tx] = src[(size_t)(k0 + r) * H_ + col0 + tx];
        }
        __syncthreads();
#pragma unroll
        for (int kk = 0; kk < 32; kk++) {
            float bv = bs[kk][tx];
#pragma unroll
            for (int e = 0; e < 4; e++) acc[e] += as[ty + e * 8][kk] * bv;
        }
        __syncthreads();
    }
#pragma unroll
    for (int e = 0; e < 4; e++)
        dst[(size_t)(row0 + ty + e * 8) * H_ + col0 + tx] = acc[e];
}

// ------- chunked scan: augmented state, fused input projection, no xw array --
// R_=64 rows/CTA, 128 CTAs, 1 CTA/SM, 8 warps; warp owns 8 rows x 256 out-cols
// (lane cols {4l..4l+3, 128+4l..128+4l+3}). z_aug row = [h(256) | x_t(8)],
// A_aug = [[Wh^T],[Wx^T]]: one K-sweep over 264 rows does h@Wh^T + x@Wx^T.
// Warps touch only their own 8 z-rows -> __syncwarp() steps, single buffer.
// PASS 0: h-part starts at 0, stores only Zend. PASS 1: from Hstart, writes out.
template <int PASS>
__global__ void __launch_bounds__(256, 1) k_scan(float* __restrict__ out) {
    extern __shared__ float zb[];             // [R_][HA]  64*264*4 = 67584 B

    const int c    = blockIdx.x & (C_ - 1);   // chunk
    const int rg   = blockIdx.x >> 5;         // row group 0..3
    const int r0   = rg * R_;
    const int tau  = threadIdx.x;
    const int w    = tau >> 5;                // warp id 0..7 -> 8 rows each
    const int l    = tau & 31;
    const int cA   = l * 4;                   // low 4 out-columns
    const int cB   = 128 + l * 4;             // high 4 out-columns

    // ---- init z buffer ----
    // h-part: PASS0 -> 0 ; PASS1 -> Hstart. (strided: row stride HA)
    for (int idx = tau; idx < R_ * (H_ / 2); idx += 256) {   // u64 elements
        int r = idx >> 7, k = idx & 127;
        unsigned long long v = 0ull;
        if (PASS == 1)
            v = ((const unsigned long long*)
                 (g_Hstart + (size_t)c * BH + (size_t)r0 * H_))[r * 128 + k];
        ((unsigned long long*)(zb + r * HA))[k] = v;
    }
    // aug-part: x at 0-based index c*L_  (used by step j=1)
    for (int idx = tau; idx < R_ * I_; idx += 256) {
        int r = idx >> 3, i = idx & 7;
        zb[r * HA + H_ + i] =
            g_xt[(size_t)(c * L_) * (B_ * I_) + (size_t)(r0 + r) * I_ + i];
    }
    __syncthreads();

    for (int j = 1; j <= L_; ++j) {
        const int t = c * L_ + j;             // global time step (1..T)
        unsigned long long acc[8][4];         // 8 rows x 4 col-u64
#pragma unroll
        for (int i = 0; i < 8; i++)
            acc[i][0] = acc[i][1] = acc[i][2] = acc[i][3] = 0ull;

        const float* zrow = zb + w * 8 * HA;
#pragma unroll 2
        for (int hg = 0; hg < HA / 4; ++hg) {      // 66 groups of 4 K-rows
            float4 z4[8];
#pragma unroll
            for (int i = 0; i < 8; i++)
                z4[i] = *(const float4*)(zrow + i * HA + hg * 4);
#pragma unroll
            for (int hh = 0; hh < 4; hh++) {
                const float* arow = g_Aaug + (hg * 4 + hh) * H_;
                ulonglong2 a_lo = *(const ulonglong2*)(arow + cA);
                ulonglong2 a_hi = *(const ulonglong2*)(arow + cB);
#pragma unroll
                for (int i = 0; i < 8; i++) {
                    float zv = (hh == 0) ? z4[i].x
                             : (hh == 1) ? z4[i].y
                             : (hh == 2) ? z4[i].z : z4[i].w;
                    unsigned long long zz = pack2(zv);
                    fma2(acc[i][0], zz, a_lo.x);
                    fma2(acc[i][1], zz, a_lo.y);
                    fma2(acc[i][2], zz, a_hi.x);
                    fma2(acc[i][3], zz, a_hi.y);
                }
            }
        }
#pragma unroll
        for (int i = 0; i < 8; i++) {
            float* zw = zb + (w * 8 + i) * HA;
            *(ulonglong2*)(zw + cA) = make_ulonglong2(acc[i][0], acc[i][1]);
            *(ulonglong2*)(zw + cB) = make_ulonglong2(acc[i][2], acc[i][3]);
            if (PASS == 1) {
                float* o = out + (size_t)t * BH + (size_t)(r0 + w * 8 + i) * H_;
                __stcs((float4*)(o + cA),
                       make_float4(lof(acc[i][0]), hif(acc[i][0]),
                                   lof(acc[i][1]), hif(acc[i][1])));
                __stcs((float4*)(o + cB),
                       make_float4(lof(acc[i][2]), hif(acc[i][2]),
                                   lof(acc[i][3]), hif(acc[i][3])));
            }
        }
        // refill aug columns with x at 0-based index t (for step j+1)
        if (j < L_ && l < 16) {
            int r8 = l >> 1, part = (l & 1) * 4;
            float4 xv = *(const float4*)
                (g_xt + (size_t)t * (B_ * I_) + (size_t)(r0 + w * 8 + r8) * I_ + part);
            *(float4*)(zb + (w * 8 + r8) * HA + H_ + part) = xv;
        }
        __syncwarp();                          // warp-local ordering only
    }

    if (PASS == 0) {
        __syncthreads();                       // all warps' final z in place
        // copy h-part (skip aug columns): row stride HA -> H_
        for (int idx = tau; idx < R_ * (H_ / 2); idx += 256) {  // u64 elements
            int r = idx >> 7, k = idx & 127;
            ((unsigned long long*)
             (g_Zend + (size_t)c * BH + (size_t)r0 * H_))[r * 128 + k] =
                ((const unsigned long long*)(zb + r * HA))[k];
        }
    }
}

// ---------------- carry: Hstart[c+1] = Hstart[c] @ A^32 + Zend[c] ----------------
__global__ void __launch_bounds__(256, 1) k_carry(const float* __restrict__ h0) {
    __shared__ float hb[2][4 * H_];
    const int r0   = blockIdx.x * 4;          // 64 blocks x 4 rows
    const int tau  = threadIdx.x;
    const int rowg = tau >> 6;                // 0..3
    const int lg   = tau & 63;
    const int c0   = lg * 4;                  // 4 output cols per thread (coalesced)

    // Hstart[0] = broadcast h0
#pragma unroll
    for (int e = 0; e < 4; e++) {
        float v = h0[tau];
        hb[0][e * H_ + tau] = v;
        g_Hstart[(size_t)(r0 + e) * H_ + tau] = v;
    }
    __syncthreads();

    int p = 0;
    for (int c = 0; c < C_ - 1; c++) {
        unsigned long long acc[2];
        const unsigned long long* zs = (const unsigned long long*)
            (g_Zend + (size_t)c * BH + (size_t)(r0 + rowg) * H_ + c0);
        acc[0] = zs[0]; acc[1] = zs[1];
        const float* zr = hb[p] + rowg * H_;
#pragma unroll 4
        for (int h = 0; h < H_; h++) {
            ulonglong2 aa = *(const ulonglong2*)(g_P32 + h * H_ + c0);
            unsigned long long zz = pack2(zr[h]);
            fma2(acc[0], zz, aa.x);
            fma2(acc[1], zz, aa.y);
        }
        unsigned long long* w = (unsigned long long*)(hb[p ^ 1] + rowg * H_ + c0);
        w[0] = acc[0]; w[1] = acc[1];
        unsigned long long* g = (unsigned long long*)
            (g_Hstart + (size_t)(c + 1) * BH + (size_t)(r0 + rowg) * H_ + c0);
        g[0] = acc[0]; g[1] = acc[1];
        __syncthreads();
        p ^= 1;
    }
}

// ---------------- launch ----------------
extern "C" void kernel_launch(void* const* d_in, const int* in_sizes, int n_in,
                              void* d_out, int out_size) {
    (void)in_sizes; (void)n_in; (void)out_size;
    const float* x  = (const float*)d_in[0];
    const float* Wh = (const float*)d_in[1];
    const float* Wx = (const float*)d_in[2];
    const float* h0 = (const float*)d_in[3];
    float* out = (float*)d_out;

    const int smem = R_ * HA * (int)sizeof(float);   // 67584 bytes
    cudaFuncSetAttribute(k_scan<0>, cudaFuncAttributeMaxDynamicSharedMemorySize, smem);
    cudaFuncSetAttribute(k_scan<1>, cudaFuncAttributeMaxDynamicSharedMemorySize, smem);

    // ncu captures MY 0-based launch index 3 -> keep k_scan<0> there.
    k_xt<<<(T_ * B_ * I_) / 256, 256>>>(x);            // 0
    k_prep<<<(HA * H_ + 255) / 256, 256>>>(Wh, Wx);    // 1
    k_out0<<<256, 256>>>(out, h0);                     // 2
    k_scan<0><<<C_ * NRG, 256, smem>>>(out);           // 3  partials -> Zend (PROFILED)
    dim3 g8(8, 8);
    k_square<<<g8, 256>>>(0);                          // 4  A^2
    k_square<<<g8, 256>>>(1);                          // 5  A^4
    k_square<<<g8, 256>>>(2);                          // 6  A^8
    k_square<<<g8, 256>>>(3);                          // 7  A^16
    k_square<<<g8, 256>>>(4);                          // 8  A^32
    k_carry<<<B_ / 4, 256>>>(h0);                      // 9  chunk start states
    k_scan<1><<<C_ * NRG, 256, smem>>>(out);           // 10 final scan -> out
}

// round 14
// speedup vs baseline: 1.9108x; 1.2301x over previous
#include <cuda_runtime.h>
#include <cstdint>
#include <cstddef>

// Problem constants
#define B_  256
#define T_  1024
#define I_  8
#define H_  256
#define HA  (H_ + I_)   // augmented state width: [h | x] = 264
#define L_  32          // steps per chunk
#define C_  32          // number of chunks (C_*L_ == T_)
#define BH  (B_*H_)
#define R_  64          // batch rows per scan CTA
#define NRG (B_/R_)     // 4 row groups -> 128 scan CTAs

// ---------------- device scratch (no allocations allowed) ----------------
__device__ float g_Aaug[HA * H_];            // rows 0..255: Wh^T ; rows 256..263: Wx^T
__device__ float g_xt[(size_t)T_ * B_ * I_]; // x transposed to (T,B,I), 8 MB
__device__ float g_Mstack[H_ * H_];          // rows m*8+i = (Wx^T A^{31-m})[i]
__device__ float g_T1[H_ * H_];
__device__ float g_T2[H_ * H_];
__device__ float g_P32[H_ * H_];             // (Wh^T)^32
__device__ float g_Zend[(size_t)C_ * BH];    // chunk-final partials (zero-init scans)
__device__ float g_Hstart[(size_t)C_ * BH];  // true chunk start states

// ---------------- packed f32x2 helpers ----------------
__device__ __forceinline__ unsigned long long pack2(float v) {
    unsigned long long r;
    asm("mov.b64 %0, {%1, %1};" : "=l"(r) : "f"(v));
    return r;
}
__device__ __forceinline__ void fma2(unsigned long long& d,
                                     unsigned long long a,
                                     unsigned long long b) {
    asm("fma.rn.f32x2 %0, %1, %2, %0;" : "+l"(d) : "l"(a), "l"(b));
}
__device__ __forceinline__ float lof(unsigned long long v) {
    return __uint_as_float((unsigned)v);
}
__device__ __forceinline__ float hif(unsigned long long v) {
    return __uint_as_float((unsigned)(v >> 32));
}

// ---------------- out[0] = broadcast h0 ----------------
__global__ void k_out0(float* __restrict__ out, const float* __restrict__ h0) {
    int idx = blockIdx.x * 256 + threadIdx.x;           // 65536 total
    out[idx] = h0[idx & (H_ - 1)];
}

// ---------------- xt[t][b][i] = x[b][t][i]  (write-coalesced) ----------------
__global__ void k_xt(const float* __restrict__ x) {
    int idx = blockIdx.x * 256 + threadIdx.x;           // 2M elements
    int i = idx & (I_ - 1);
    int b = (idx >> 3) & (B_ - 1);
    int t = idx >> 11;
    g_xt[idx] = x[((size_t)b * T_ + t) * I_ + i];
}

// ---------------- build A_aug: rows 0..255 = Wh^T, rows 256..263 = Wx^T ------
__global__ void k_prep(const float* __restrict__ Wh, const float* __restrict__ Wx) {
    int idx = blockIdx.x * 256 + threadIdx.x;           // HA*H_ = 67584
    if (idx < H_ * H_) {
        int h  = idx >> 8;
        int c  = idx & 255;
        g_Aaug[idx] = Wh[c * H_ + h];                   // (Wh^T)[h][c]
    } else if (idx < HA * H_) {
        int r  = idx >> 8;                              // 256..263
        int c  = idx & 255;
        g_Aaug[idx] = Wx[c * I_ + (r - H_)];            // (Wx^T)[i][c]
    }
}

// ---------------- Mstack: V_k = Wx^T A^k, stored at row block (31-k)*8 -------
// 1 CTA, 256 threads (thread = output column). Serial over k (true dependency).
__global__ void __launch_bounds__(256, 1) k_mstack() {
    __shared__ float V[I_][H_];
    const int c = threadIdx.x;
#pragma unroll
    for (int i = 0; i < I_; i++) V[i][c] = g_Aaug[(H_ + i) * H_ + c];
    __syncthreads();

    for (int k = 0; k < L_; k++) {
        const int m = L_ - 1 - k;
#pragma unroll
        for (int i = 0; i < I_; i++)
            g_Mstack[(m * I_ + i) * H_ + c] = V[i][c];
        if (k == L_ - 1) break;
        float acc[I_] = {0.f, 0.f, 0.f, 0.f, 0.f, 0.f, 0.f, 0.f};
#pragma unroll 8
        for (int h = 0; h < H_; h++) {
            float a = g_Aaug[h * H_ + c];
#pragma unroll
            for (int i = 0; i < I_; i++) acc[i] += V[i][h] * a;
        }
        __syncthreads();
#pragma unroll
        for (int i = 0; i < I_; i++) V[i][c] = acc[i];
        __syncthreads();
    }
}

// ---------------- Zend[c] = Xwin_c @ Mstack  (replaces scan pass 0) ----------
// Xwin_c[b][kk] = x[b][c*L + (kk>>3)][kk&7] -> contiguous: x[b*T*I + c*L*I + kk]
__global__ void k_zend(const float* __restrict__ x) {
    const int c = blockIdx.z;                 // chunk
    __shared__ float as[32][33], bs[32][33];
    const int tx = threadIdx.x & 31;
    const int ty = threadIdx.x >> 5;          // 0..7
    const int row0 = blockIdx.y * 32, col0 = blockIdx.x * 32;
    float acc[4] = {0.f, 0.f, 0.f, 0.f};
    for (int k0 = 0; k0 < H_; k0 += 32) {
#pragma unroll
        for (int e = 0; e < 4; e++) {
            int r = ty + e * 8;
            as[r][tx] = x[(size_t)(row0 + r) * (T_ * I_) + c * (L_ * I_) + k0 + tx];
            bs[r][tx] = g_Mstack[(size_t)(k0 + r) * H_ + col0 + tx];
        }
        __syncthreads();
#pragma unroll
        for (int kk = 0; kk < 32; kk++) {
            float bv = bs[kk][tx];
#pragma unroll
            for (int e = 0; e < 4; e++) acc[e] += as[ty + e * 8][kk] * bv;
        }
        __syncthreads();
    }
#pragma unroll
    for (int e = 0; e < 4; e++)
        g_Zend[(size_t)c * BH + (size_t)(row0 + ty + e * 8) * H_ + col0 + tx] = acc[e];
}

// ---------------- squaring chain for (Wh^T)^32 ----------------
__global__ void k_square(int step) {
    const float* src;
    float* dst;
    switch (step) {
        case 0: src = g_Aaug; dst = g_T1;  break;  // A^2 (first 256 rows = Wh^T)
        case 1: src = g_T1;   dst = g_T2;  break;  // A^4
        case 2: src = g_T2;   dst = g_T1;  break;  // A^8
        case 3: src = g_T1;   dst = g_T2;  break;  // A^16
        default:src = g_T2;   dst = g_P32; break;  // A^32
    }
    __shared__ float as[32][33], bs[32][33];
    const int tx = threadIdx.x & 31;
    const int ty = threadIdx.x >> 5;            // 0..7
    const int row0 = blockIdx.y * 32, col0 = blockIdx.x * 32;
    float acc[4] = {0.f, 0.f, 0.f, 0.f};
    for (int k0 = 0; k0 < H_; k0 += 32) {
#pragma unroll
        for (int e = 0; e < 4; e++) {
            int r = ty + e * 8;
            as[r][tx] = src[(size_t)(row0 + r) * H_ + k0 + tx];
            bs[r][tx] = src[(size_t)(k0 + r) * H_ + col0 + tx];
        }
        __syncthreads();
#pragma unroll
        for (int kk = 0; kk < 32; kk++) {
            float bv = bs[kk][tx];
#pragma unroll
            for (int e = 0; e < 4; e++) acc[e] += as[ty + e * 8][kk] * bv;
        }
        __syncthreads();
    }
#pragma unroll
    for (int e = 0; e < 4; e++)
        dst[(size_t)(row0 + ty + e * 8) * H_ + col0 + tx] = acc[e];
}

// ------- scan pass 1: augmented state, fused input projection ---------------
// (identical inner structure to the validated R13 kernel; only PASS=1 is used)
template <int PASS>
__global__ void __launch_bounds__(256, 1) k_scan(float* __restrict__ out) {
    extern __shared__ float zb[];             // [R_][HA]  64*264*4 = 67584 B

    const int c    = blockIdx.x & (C_ - 1);   // chunk
    const int rg   = blockIdx.x >> 5;         // row group 0..3
    const int r0   = rg * R_;
    const int tau  = threadIdx.x;
    const int w    = tau >> 5;                // warp id 0..7 -> 8 rows each
    const int l    = tau & 31;
    const int cA   = l * 4;                   // low 4 out-columns
    const int cB   = 128 + l * 4;             // high 4 out-columns

    // ---- init z buffer ----
    for (int idx = tau; idx < R_ * (H_ / 2); idx += 256) {   // u64 elements
        int r = idx >> 7, k = idx & 127;
        unsigned long long v = 0ull;
        if (PASS == 1)
            v = ((const unsigned long long*)
                 (g_Hstart + (size_t)c * BH + (size_t)r0 * H_))[r * 128 + k];
        ((unsigned long long*)(zb + r * HA))[k] = v;
    }
    for (int idx = tau; idx < R_ * I_; idx += 256) {
        int r = idx >> 3, i = idx & 7;
        zb[r * HA + H_ + i] =
            g_xt[(size_t)(c * L_) * (B_ * I_) + (size_t)(r0 + r) * I_ + i];
    }
    __syncthreads();

    for (int j = 1; j <= L_; ++j) {
        const int t = c * L_ + j;             // global time step (1..T)
        unsigned long long acc[8][4];         // 8 rows x 4 col-u64
#pragma unroll
        for (int i = 0; i < 8; i++)
            acc[i][0] = acc[i][1] = acc[i][2] = acc[i][3] = 0ull;

        const float* zrow = zb + w * 8 * HA;
#pragma unroll 2
        for (int hg = 0; hg < HA / 4; ++hg) {      // 66 groups of 4 K-rows
            float4 z4[8];
#pragma unroll
            for (int i = 0; i < 8; i++)
                z4[i] = *(const float4*)(zrow + i * HA + hg * 4);
#pragma unroll
            for (int hh = 0; hh < 4; hh++) {
                const float* arow = g_Aaug + (hg * 4 + hh) * H_;
                ulonglong2 a_lo = *(const ulonglong2*)(arow + cA);
                ulonglong2 a_hi = *(const ulonglong2*)(arow + cB);
#pragma unroll
                for (int i = 0; i < 8; i++) {
                    float zv = (hh == 0) ? z4[i].x
                             : (hh == 1) ? z4[i].y
                             : (hh == 2) ? z4[i].z : z4[i].w;
                    unsigned long long zz = pack2(zv);
                    fma2(acc[i][0], zz, a_lo.x);
                    fma2(acc[i][1], zz, a_lo.y);
                    fma2(acc[i][2], zz, a_hi.x);
                    fma2(acc[i][3], zz, a_hi.y);
                }
            }
        }
#pragma unroll
        for (int i = 0; i < 8; i++) {
            float* zw = zb + (w * 8 + i) * HA;
            *(ulonglong2*)(zw + cA) = make_ulonglong2(acc[i][0], acc[i][1]);
            *(ulonglong2*)(zw + cB) = make_ulonglong2(acc[i][2], acc[i][3]);
            if (PASS == 1) {
                float* o = out + (size_t)t * BH + (size_t)(r0 + w * 8 + i) * H_;
                __stcs((float4*)(o + cA),
                       make_float4(lof(acc[i][0]), hif(acc[i][0]),
                                   lof(acc[i][1]), hif(acc[i][1])));
                __stcs((float4*)(o + cB),
                       make_float4(lof(acc[i][2]), hif(acc[i][2]),
                                   lof(acc[i][3]), hif(acc[i][3])));
            }
        }
        // refill aug columns with x at 0-based index t (for step j+1)
        if (j < L_ && l < 16) {
            int r8 = l >> 1, part = (l & 1) * 4;
            float4 xv = *(const float4*)
                (g_xt + (size_t)t * (B_ * I_) + (size_t)(r0 + w * 8 + r8) * I_ + part);
            *(float4*)(zb + (w * 8 + r8) * HA + H_ + part) = xv;
        }
        __syncwarp();                          // warp-local ordering only
    }
}

// ---------------- carry: Hstart[c+1] = Hstart[c] @ A^32 + Zend[c] ----------------
__global__ void __launch_bounds__(256, 1) k_carry(const float* __restrict__ h0) {
    __shared__ float hb[2][4 * H_];
    const int r0   = blockIdx.x * 4;          // 64 blocks x 4 rows
    const int tau  = threadIdx.x;
    const int rowg = tau >> 6;                // 0..3
    const int lg   = tau & 63;
    const int c0   = lg * 4;                  // 4 output cols per thread (coalesced)

    // Hstart[0] = broadcast h0
#pragma unroll
    for (int e = 0; e < 4; e++) {
        float v = h0[tau];
        hb[0][e * H_ + tau] = v;
        g_Hstart[(size_t)(r0 + e) * H_ + tau] = v;
    }
    __syncthreads();

    int p = 0;
    for (int c = 0; c < C_ - 1; c++) {
        unsigned long long acc[2];
        const unsigned long long* zs = (const unsigned long long*)
            (g_Zend + (size_t)c * BH + (size_t)(r0 + rowg) * H_ + c0);
        acc[0] = zs[0]; acc[1] = zs[1];
        const float* zr = hb[p] + rowg * H_;
#pragma unroll 4
        for (int h = 0; h < H_; h++) {
            ulonglong2 aa = *(const ulonglong2*)(g_P32 + h * H_ + c0);
            unsigned long long zz = pack2(zr[h]);
            fma2(acc[0], zz, aa.x);
            fma2(acc[1], zz, aa.y);
        }
        unsigned long long* w = (unsigned long long*)(hb[p ^ 1] + rowg * H_ + c0);
        w[0] = acc[0]; w[1] = acc[1];
        unsigned long long* g = (unsigned long long*)
            (g_Hstart + (size_t)(c + 1) * BH + (size_t)(r0 + rowg) * H_ + c0);
        g[0] = acc[0]; g[1] = acc[1];
        __syncthreads();
        p ^= 1;
    }
}

// ---------------- launch ----------------
extern "C" void kernel_launch(void* const* d_in, const int* in_sizes, int n_in,
                              void* d_out, int out_size) {
    (void)in_sizes; (void)n_in; (void)out_size;
    const float* x  = (const float*)d_in[0];
    const float* Wh = (const float*)d_in[1];
    const float* Wx = (const float*)d_in[2];
    const float* h0 = (const float*)d_in[3];
    float* out = (float*)d_out;

    const int smem = R_ * HA * (int)sizeof(float);   // 67584 bytes
    cudaFuncSetAttribute(k_scan<1>, cudaFuncAttributeMaxDynamicSharedMemorySize, smem);

    // ncu captures MY 0-based launch index 3 -> k_zend gets profiled.
    k_prep<<<(HA * H_ + 255) / 256, 256>>>(Wh, Wx);    // 0
    k_mstack<<<1, 256>>>();                            // 1  Wx^T A^k stack
    k_xt<<<(T_ * B_ * I_) / 256, 256>>>(x);            // 2
    dim3 gz(8, 8, 32);
    k_zend<<<gz, 256>>>(x);                            // 3  Zend GEMM (PROFILED)
    dim3 g8(8, 8);
    k_square<<<g8, 256>>>(0);                          // 4  A^2
    k_square<<<g8, 256>>>(1);                          // 5  A^4
    k_square<<<g8, 256>>>(2);                          // 6  A^8
    k_square<<<g8, 256>>>(3);                          // 7  A^16
    k_square<<<g8, 256>>>(4);                          // 8  A^32
    k_out0<<<256, 256>>>(out, h0);                     // 9
    k_carry<<<B_ / 4, 256>>>(h0);                      // 10 chunk start states
    k_scan<1><<<C_ * NRG, 256, smem>>>(out);           // 11 final scan -> out
}

// round 15
// speedup vs baseline: 2.3114x; 1.2096x over previous
#include <cuda_runtime.h>
#include <cstdint>
#include <cstddef>

// Problem constants
#define B_  256
#define T_  1024
#define I_  8
#define H_  256
#define HA  (H_ + I_)   // augmented state width: [h | x] = 264
#define L_  32          // steps per chunk
#define C_  32          // number of chunks (C_*L_ == T_)
#define BH  (B_*H_)
#define R_  64          // batch rows per scan CTA
#define NRG (B_/R_)     // 4 row groups -> 128 scan CTAs

// ---------------- device scratch (no allocations allowed) ----------------
__device__ float g_Aaug[HA * H_];            // rows 0..255: Wh^T ; rows 256..263: Wx^T
__device__ float g_xt[(size_t)T_ * B_ * I_]; // x transposed to (T,B,I), 8 MB
__device__ float g_Mstack[H_ * H_];          // row block (31-k)*8 holds Wx^T A^k
__device__ float g_P2[H_ * H_];
__device__ float g_P4[H_ * H_];
__device__ float g_P8[H_ * H_];
__device__ float g_P16[H_ * H_];
__device__ float g_P32[H_ * H_];             // (Wh^T)^32
__device__ float g_Zend[(size_t)C_ * BH];    // chunk-final partials
__device__ float g_Hstart[(size_t)C_ * BH];  // true chunk start states

// ---------------- packed f32x2 helpers ----------------
__device__ __forceinline__ unsigned long long pack2(float v) {
    unsigned long long r;
    asm("mov.b64 %0, {%1, %1};" : "=l"(r) : "f"(v));
    return r;
}
__device__ __forceinline__ void fma2(unsigned long long& d,
                                     unsigned long long a,
                                     unsigned long long b) {
    asm("fma.rn.f32x2 %0, %1, %2, %0;" : "+l"(d) : "l"(a), "l"(b));
}
__device__ __forceinline__ float lof(unsigned long long v) {
    return __uint_as_float((unsigned)v);
}
__device__ __forceinline__ float hif(unsigned long long v) {
    return __uint_as_float((unsigned)(v >> 32));
}

// ---------------- out[0] = broadcast h0 ----------------
__global__ void k_out0(float* __restrict__ out, const float* __restrict__ h0) {
    int idx = blockIdx.x * 256 + threadIdx.x;           // 65536 total
    out[idx] = h0[idx & (H_ - 1)];
}

// ---------------- xt[t][b][i] = x[b][t][i]  (write-coalesced) ----------------
__global__ void k_xt(const float* __restrict__ x) {
    int idx = blockIdx.x * 256 + threadIdx.x;           // 2M elements
    int i = idx & (I_ - 1);
    int b = (idx >> 3) & (B_ - 1);
    int t = idx >> 11;
    g_xt[idx] = x[((size_t)b * T_ + t) * I_ + i];
}

// ---- build A_aug (rows 0..255 = Wh^T, 256..263 = Wx^T) + seed Mstack V_0 ----
__global__ void k_prep(const float* __restrict__ Wh, const float* __restrict__ Wx) {
    int idx = blockIdx.x * 256 + threadIdx.x;           // HA*H_ = 67584
    if (idx < H_ * H_) {
        int h  = idx >> 8;
        int c  = idx & 255;
        g_Aaug[idx] = Wh[c * H_ + h];                   // (Wh^T)[h][c]
    } else if (idx < HA * H_) {
        int r  = idx >> 8;                              // 256..263
        int c  = idx & 255;
        float v = Wx[c * I_ + (r - H_)];                // (Wx^T)[i][c]
        g_Aaug[idx] = v;
        // V_0 = Wx^T  -> Mstack row block 31
        g_Mstack[((L_ - 1) * I_ + (r - H_)) * H_ + c] = v;
    }
}

// ---------------- squaring chain: dedicated buffers ----------------
// step 0: A->P2, 1: P2->P4, 2: P4->P8, 3: P8->P16, 4: P16->P32
__global__ void k_square(int step) {
    const float* src;
    float* dst;
    switch (step) {
        case 0: src = g_Aaug; dst = g_P2;  break;
        case 1: src = g_P2;   dst = g_P4;  break;
        case 2: src = g_P4;   dst = g_P8;  break;
        case 3: src = g_P8;   dst = g_P16; break;
        default:src = g_P16;  dst = g_P32; break;
    }
    __shared__ float as[32][33], bs[32][33];
    const int tx = threadIdx.x & 31;
    const int ty = threadIdx.x >> 5;            // 0..7
    const int row0 = blockIdx.y * 32, col0 = blockIdx.x * 32;
    float acc[4] = {0.f, 0.f, 0.f, 0.f};
    for (int k0 = 0; k0 < H_; k0 += 32) {
#pragma unroll
        for (int e = 0; e < 4; e++) {
            int r = ty + e * 8;
            as[r][tx] = src[(size_t)(row0 + r) * H_ + k0 + tx];
            bs[r][tx] = src[(size_t)(k0 + r) * H_ + col0 + tx];
        }
        __syncthreads();
#pragma unroll
        for (int kk = 0; kk < 32; kk++) {
            float bv = bs[kk][tx];
#pragma unroll
            for (int e = 0; e < 4; e++) acc[e] += as[ty + e * 8][kk] * bv;
        }
        __syncthreads();
    }
#pragma unroll
    for (int e = 0; e < 4; e++)
        dst[(size_t)(row0 + ty + e * 8) * H_ + col0 + tx] = acc[e];
}

// ---------------- Mstack doubling stage ----------------
// stage m: for k = 0..2^m-1 (parallel CTAs): V_{k+2^m} = V_k @ A^{2^m}
// V_k lives at Mstack row block (31-k)*8.
__global__ void __launch_bounds__(256, 1) k_vstage(int stage) {
    const int nk = 1 << stage;
    const float* P;
    switch (stage) {
        case 0: P = g_Aaug; break;   // A   (rows 0..255)
        case 1: P = g_P2;   break;   // A^2
        case 2: P = g_P4;   break;   // A^4
        case 3: P = g_P8;   break;   // A^8
        default:P = g_P16;  break;   // A^16
    }
    const int k = blockIdx.x;        // 0..nk-1
    const int c = threadIdx.x;       // output column
    __shared__ float V[I_][H_];
    const float* src = g_Mstack + (size_t)((L_ - 1 - k) * I_) * H_;
#pragma unroll
    for (int i = 0; i < I_; i++) V[i][c] = src[i * H_ + c];
    __syncthreads();

    float acc[I_] = {0.f, 0.f, 0.f, 0.f, 0.f, 0.f, 0.f, 0.f};
#pragma unroll 8
    for (int h = 0; h < H_; h++) {
        float a = P[h * H_ + c];
#pragma unroll
        for (int i = 0; i < I_; i++) acc[i] += V[i][h] * a;
    }
    float* dst = g_Mstack + (size_t)((L_ - 1 - k - nk) * I_) * H_;
#pragma unroll
    for (int i = 0; i < I_; i++) dst[i * H_ + c] = acc[i];
}

// ---------------- Zend[c] = Xwin_c @ Mstack  (replaces scan pass 0) ----------
__global__ void k_zend(const float* __restrict__ x) {
    const int c = blockIdx.z;                 // chunk
    __shared__ float as[32][33], bs[32][33];
    const int tx = threadIdx.x & 31;
    const int ty = threadIdx.x >> 5;          // 0..7
    const int row0 = blockIdx.y * 32, col0 = blockIdx.x * 32;
    float acc[4] = {0.f, 0.f, 0.f, 0.f};
    for (int k0 = 0; k0 < H_; k0 += 32) {
#pragma unroll
        for (int e = 0; e < 4; e++) {
            int r = ty + e * 8;
            as[r][tx] = x[(size_t)(row0 + r) * (T_ * I_) + c * (L_ * I_) + k0 + tx];
            bs[r][tx] = g_Mstack[(size_t)(k0 + r) * H_ + col0 + tx];
        }
        __syncthreads();
#pragma unroll
        for (int kk = 0; kk < 32; kk++) {
            float bv = bs[kk][tx];
#pragma unroll
            for (int e = 0; e < 4; e++) acc[e] += as[ty + e * 8][kk] * bv;
        }
        __syncthreads();
    }
#pragma unroll
    for (int e = 0; e < 4; e++)
        g_Zend[(size_t)c * BH + (size_t)(row0 + ty + e * 8) * H_ + col0 + tx] = acc[e];
}

// ------- scan pass 1: augmented state, fused input projection ---------------
template <int PASS>
__global__ void __launch_bounds__(256, 1) k_scan(float* __restrict__ out) {
    extern __shared__ float zb[];             // [R_][HA]  64*264*4 = 67584 B

    const int c    = blockIdx.x & (C_ - 1);   // chunk
    const int rg   = blockIdx.x >> 5;         // row group 0..3
    const int r0   = rg * R_;
    const int tau  = threadIdx.x;
    const int w    = tau >> 5;                // warp id 0..7 -> 8 rows each
    const int l    = tau & 31;
    const int cA   = l * 4;                   // low 4 out-columns
    const int cB   = 128 + l * 4;             // high 4 out-columns

    // ---- init z buffer ----
    for (int idx = tau; idx < R_ * (H_ / 2); idx += 256) {   // u64 elements
        int r = idx >> 7, k = idx & 127;
        unsigned long long v = 0ull;
        if (PASS == 1)
            v = ((const unsigned long long*)
                 (g_Hstart + (size_t)c * BH + (size_t)r0 * H_))[r * 128 + k];
        ((unsigned long long*)(zb + r * HA))[k] = v;
    }
    for (int idx = tau; idx < R_ * I_; idx += 256) {
        int r = idx >> 3, i = idx & 7;
        zb[r * HA + H_ + i] =
            g_xt[(size_t)(c * L_) * (B_ * I_) + (size_t)(r0 + r) * I_ + i];
    }
    __syncthreads();

    for (int j = 1; j <= L_; ++j) {
        const int t = c * L_ + j;             // global time step (1..T)
        unsigned long long acc[8][4];         // 8 rows x 4 col-u64
#pragma unroll
        for (int i = 0; i < 8; i++)
            acc[i][0] = acc[i][1] = acc[i][2] = acc[i][3] = 0ull;

        const float* zrow = zb + w * 8 * HA;
#pragma unroll 2
        for (int hg = 0; hg < HA / 4; ++hg) {      // 66 groups of 4 K-rows
            float4 z4[8];
#pragma unroll
            for (int i = 0; i < 8; i++)
                z4[i] = *(const float4*)(zrow + i * HA + hg * 4);
#pragma unroll
            for (int hh = 0; hh < 4; hh++) {
                const float* arow = g_Aaug + (hg * 4 + hh) * H_;
                ulonglong2 a_lo = *(const ulonglong2*)(arow + cA);
                ulonglong2 a_hi = *(const ulonglong2*)(arow + cB);
#pragma unroll
                for (int i = 0; i < 8; i++) {
                    float zv = (hh == 0) ? z4[i].x
                             : (hh == 1) ? z4[i].y
                             : (hh == 2) ? z4[i].z : z4[i].w;
                    unsigned long long zz = pack2(zv);
                    fma2(acc[i][0], zz, a_lo.x);
                    fma2(acc[i][1], zz, a_lo.y);
                    fma2(acc[i][2], zz, a_hi.x);
                    fma2(acc[i][3], zz, a_hi.y);
                }
            }
        }
#pragma unroll
        for (int i = 0; i < 8; i++) {
            float* zw = zb + (w * 8 + i) * HA;
            *(ulonglong2*)(zw + cA) = make_ulonglong2(acc[i][0], acc[i][1]);
            *(ulonglong2*)(zw + cB) = make_ulonglong2(acc[i][2], acc[i][3]);
            if (PASS == 1) {
                float* o = out + (size_t)t * BH + (size_t)(r0 + w * 8 + i) * H_;
                __stcs((float4*)(o + cA),
                       make_float4(lof(acc[i][0]), hif(acc[i][0]),
                                   lof(acc[i][1]), hif(acc[i][1])));
                __stcs((float4*)(o + cB),
                       make_float4(lof(acc[i][2]), hif(acc[i][2]),
                                   lof(acc[i][3]), hif(acc[i][3])));
            }
        }
        // refill aug columns with x at 0-based index t (for step j+1)
        if (j < L_ && l < 16) {
            int r8 = l >> 1, part = (l & 1) * 4;
            float4 xv = *(const float4*)
                (g_xt + (size_t)t * (B_ * I_) + (size_t)(r0 + w * 8 + r8) * I_ + part);
            *(float4*)(zb + (w * 8 + r8) * HA + H_ + part) = xv;
        }
        __syncwarp();                          // warp-local ordering only
    }
}

// ---------------- carry: Hstart[c+1] = Hstart[c] @ A^32 + Zend[c] ----------------
__global__ void __launch_bounds__(256, 1) k_carry(const float* __restrict__ h0) {
    __shared__ float hb[2][4 * H_];
    const int r0   = blockIdx.x * 4;          // 64 blocks x 4 rows
    const int tau  = threadIdx.x;
    const int rowg = tau >> 6;                // 0..3
    const int lg   = tau & 63;
    const int c0   = lg * 4;                  // 4 output cols per thread (coalesced)

    // Hstart[0] = broadcast h0
#pragma unroll
    for (int e = 0; e < 4; e++) {
        float v = h0[tau];
        hb[0][e * H_ + tau] = v;
        g_Hstart[(size_t)(r0 + e) * H_ + tau] = v;
    }
    __syncthreads();

    int p = 0;
    for (int c = 0; c < C_ - 1; c++) {
        unsigned long long acc[2];
        const unsigned long long* zs = (const unsigned long long*)
            (g_Zend + (size_t)c * BH + (size_t)(r0 + rowg) * H_ + c0);
        acc[0] = zs[0]; acc[1] = zs[1];
        const float* zr = hb[p] + rowg * H_;
#pragma unroll 4
        for (int h = 0; h < H_; h++) {
            ulonglong2 aa = *(const ulonglong2*)(g_P32 + h * H_ + c0);
            unsigned long long zz = pack2(zr[h]);
            fma2(acc[0], zz, aa.x);
            fma2(acc[1], zz, aa.y);
        }
        unsigned long long* w = (unsigned long long*)(hb[p ^ 1] + rowg * H_ + c0);
        w[0] = acc[0]; w[1] = acc[1];
        unsigned long long* g = (unsigned long long*)
            (g_Hstart + (size_t)(c + 1) * BH + (size_t)(r0 + rowg) * H_ + c0);
        g[0] = acc[0]; g[1] = acc[1];
        __syncthreads();
        p ^= 1;
    }
}

// ---------------- launch ----------------
extern "C" void kernel_launch(void* const* d_in, const int* in_sizes, int n_in,
                              void* d_out, int out_size) {
    (void)in_sizes; (void)n_in; (void)out_size;
    const float* x  = (const float*)d_in[0];
    const float* Wh = (const float*)d_in[1];
    const float* Wx = (const float*)d_in[2];
    const float* h0 = (const float*)d_in[3];
    float* out = (float*)d_out;

    const int smem = R_ * HA * (int)sizeof(float);   // 67584 bytes
    cudaFuncSetAttribute(k_scan<1>, cudaFuncAttributeMaxDynamicSharedMemorySize, smem);

    dim3 g8(8, 8);
    k_prep<<<(HA * H_ + 255) / 256, 256>>>(Wh, Wx);    // 0  Aaug + V_0
    k_xt<<<(T_ * B_ * I_) / 256, 256>>>(x);            // 1
    k_square<<<g8, 256>>>(0);                          // 2  A^2
    k_square<<<g8, 256>>>(1);                          // 3  A^4
    k_square<<<g8, 256>>>(2);                          // 4  A^8
    k_square<<<g8, 256>>>(3);                          // 5  A^16
    k_square<<<g8, 256>>>(4);                          // 6  A^32
    k_vstage<<<1, 256>>>(0);                           // 7  V_1
    k_vstage<<<2, 256>>>(1);                           // 8  V_2..3
    k_vstage<<<4, 256>>>(2);                           // 9  V_4..7
    k_vstage<<<8, 256>>>(3);                           // 10 V_8..15
    k_vstage<<<16, 256>>>(4);                          // 11 V_16..31
    dim3 gz(8, 8, 32);
    k_zend<<<gz, 256>>>(x);                            // 12 Zend GEMM
    k_out0<<<256, 256>>>(out, h0);                     // 13
    k_carry<<<B_ / 4, 256>>>(h0);                      // 14 chunk start states
    k_scan<1><<<C_ * NRG, 256, smem>>>(out);           // 15 final scan -> out
}